// round 5
// baseline (speedup 1.0000x reference)
#include <cuda_runtime.h>
#include <cuda_fp16.h>
#include <math.h>
#include <cstdint>

#define S_  256
#define I_  512
#define CM  64
#define CZ  128
#define H_  8
#define CH  32
#define HC  256
#define NN  (S_*CH)   // 8192
#define EPS 1e-5f

// ---- scratch ----
__device__ float  d_mln[(size_t)S_*I_*CM];
__device__ __half d_vh[(size_t)H_*NN*I_];     // v fp16 [h][n][j], n = s*32+c
__device__ float  d_gbuf[(size_t)S_*I_*HC];   // sigmoid(g) fp32 [s*i][hc]
__device__ float  d_bw[(size_t)H_*I_*I_];     // b fp32 [h][i][j]
__device__ __half d_wh[(size_t)H_*I_*I_];     // softmax(w) fp16 [h][i][j]
__device__ __half d_oh[(size_t)H_*I_*NN];     // o fp16 [h][i][n]

__device__ __forceinline__ float warp_sum(float v) {
#pragma unroll
    for (int o = 16; o; o >>= 1) v += __shfl_xor_sync(0xffffffffu, v, o);
    return v;
}
__device__ __forceinline__ float warp_max(float v) {
#pragma unroll
    for (int o = 16; o; o >>= 1) v = fmaxf(v, __shfl_xor_sync(0xffffffffu, v, o));
    return v;
}
__device__ __forceinline__ unsigned f2tf(float x) {
    unsigned r; asm("cvt.rna.tf32.f32 %0, %1;" : "=r"(r) : "f"(x)); return r;
}
__device__ __forceinline__ float tfs(float x) { return __uint_as_float(f2tf(x)); }

#define MMA_TF32(d0,d1,d2,d3,a0,a1,a2,a3,b0,b1) \
    asm volatile("mma.sync.aligned.m16n8k8.row.col.f32.tf32.tf32.f32 " \
                 "{%0,%1,%2,%3},{%4,%5,%6,%7},{%8,%9},{%0,%1,%2,%3};" \
                 : "+f"(d0),"+f"(d1),"+f"(d2),"+f"(d3) \
                 : "r"(a0),"r"(a1),"r"(a2),"r"(a3),"r"(b0),"r"(b1))

#define MMA_F16(d0,d1,d2,d3,a0,a1,a2,a3,b0,b1) \
    asm volatile("mma.sync.aligned.m16n8k16.row.col.f32.f16.f16.f32 " \
                 "{%0,%1,%2,%3},{%4,%5,%6,%7},{%8,%9},{%0,%1,%2,%3};" \
                 : "+f"(d0),"+f"(d1),"+f"(d2),"+f"(d3) \
                 : "r"(a0),"r"(a1),"r"(a2),"r"(a3),"r"(b0),"r"(b1))

// ---------------- K1: LayerNorm(m) ----------------
__global__ void k_ln_m(const float* __restrict__ m, const float* __restrict__ g,
                       const float* __restrict__ b) {
    int row  = blockIdx.x * 8 + (threadIdx.x >> 5);
    int lane = threadIdx.x & 31;
    const float* x = m + (size_t)row * CM;
    float v0 = x[lane], v1 = x[lane + 32];
    float mu = warp_sum(v0 + v1) * (1.f / 64.f);
    float d0 = v0 - mu, d1 = v1 - mu;
    float var = warp_sum(d0 * d0 + d1 * d1) * (1.f / 64.f);
    float rs = rsqrtf(var + EPS);
    float* y = d_mln + (size_t)row * CM;
    y[lane]      = d0 * rs * g[lane]      + b[lane];
    y[lane + 32] = d1 * rs * g[lane + 32] + b[lane + 32];
}

// ------- K2: fused v+g projection, tf32 MMA; v staged via smem -> coalesced fp16 -------
// grid (4, 1024): bx 0,1 = v cols [0,256); bx 2,3 = g cols [0,256).
__global__ void __launch_bounds__(256, 2) k_vg_tc(const float* __restrict__ Wv,
                                                  const float* __restrict__ Wg,
                                                  const float* __restrict__ msk) {
    extern __shared__ float sm[];
    float (*As)[68]  = (float(*)[68])sm;
    float (*Bs)[132] = (float(*)[132])(sm + 128 * 68);
    int t = threadIdx.x;
    int lane = t & 31, warp = t >> 5;
    int g = lane >> 2, tg = lane & 3;
    int wr = warp >> 2, wc = warp & 3;
    int mBase = blockIdx.y * 128, nBase = blockIdx.x * 128;
    bool isV = (blockIdx.x < 2);

#pragma unroll
    for (int q = 0; q < 8; q++) {
        int i = q * 256 + t;
        int mm = i >> 4, kf = i & 15;
        float4 v4 = *(const float4*)(d_mln + (size_t)(mBase + mm) * CM + kf * 4);
        *(float4*)&As[mm][kf * 4] = make_float4(tfs(v4.x), tfs(v4.y), tfs(v4.z), tfs(v4.w));
    }
#pragma unroll
    for (int q = 0; q < 8; q++) {
        int i = q * 256 + t;
        int n = i & 127, kf = i >> 7;
        int col = nBase + n;
        const float* Wp = (col < 256) ? (Wv + (size_t)col * CM)
                                      : (Wg + (size_t)(col - 256) * CM);
        float4 v4 = *(const float4*)(Wp + kf * 4);
        Bs[kf * 4 + 0][n] = tfs(v4.x);
        Bs[kf * 4 + 1][n] = tfs(v4.y);
        Bs[kf * 4 + 2][n] = tfs(v4.z);
        Bs[kf * 4 + 3][n] = tfs(v4.w);
    }
    __syncthreads();

    float acc[4][4][4];
#pragma unroll
    for (int a = 0; a < 4; a++)
#pragma unroll
        for (int b = 0; b < 4; b++)
#pragma unroll
            for (int c = 0; c < 4; c++) acc[a][b][c] = 0.f;

#pragma unroll
    for (int ks = 0; ks < 8; ks++) {
        int kk = ks * 8;
        unsigned Af[4][4], Bf[4][2];
#pragma unroll
        for (int mt = 0; mt < 4; mt++) {
            int m0 = wr * 64 + mt * 16;
            Af[mt][0] = __float_as_uint(As[m0 + g][kk + tg]);
            Af[mt][1] = __float_as_uint(As[m0 + g + 8][kk + tg]);
            Af[mt][2] = __float_as_uint(As[m0 + g][kk + tg + 4]);
            Af[mt][3] = __float_as_uint(As[m0 + g + 8][kk + tg + 4]);
        }
#pragma unroll
        for (int nt = 0; nt < 4; nt++) {
            int n0 = wc * 32 + nt * 8;
            Bf[nt][0] = __float_as_uint(Bs[kk + tg][n0 + g]);
            Bf[nt][1] = __float_as_uint(Bs[kk + tg + 4][n0 + g]);
        }
#pragma unroll
        for (int mt = 0; mt < 4; mt++)
#pragma unroll
            for (int nt = 0; nt < 4; nt++)
                MMA_TF32(acc[mt][nt][0], acc[mt][nt][1], acc[mt][nt][2], acc[mt][nt][3],
                         Af[mt][0], Af[mt][1], Af[mt][2], Af[mt][3],
                         Bf[nt][0], Bf[nt][1]);
    }

    if (isV) {
        // stage transposed tile T[col_local][j_local] fp16, then coalesced writeout
        __syncthreads();                       // smem reuse
        __half (*T)[136] = (__half(*)[136])sm; // 128x136 halves = 34 KB
#pragma unroll
        for (int mt = 0; mt < 4; mt++) {
            int r0l = wr * 64 + mt * 16 + g, r1l = r0l + 8;
            float mk0 = msk[mBase + r0l], mk1 = msk[mBase + r1l];
#pragma unroll
            for (int nt = 0; nt < 4; nt++) {
                int cl = wc * 32 + nt * 8 + 2 * tg;
                T[cl][r0l]     = __float2half(acc[mt][nt][0] * mk0);
                T[cl + 1][r0l] = __float2half(acc[mt][nt][1] * mk0);
                T[cl][r1l]     = __float2half(acc[mt][nt][2] * mk1);
                T[cl + 1][r1l] = __float2half(acc[mt][nt][3] * mk1);
            }
        }
        __syncthreads();
        int row = t >> 1, part = t & 1;
        int Cc = nBase + row;
        int hh = Cc >> 5, c = Cc & 31;
        int s = mBase >> 9, j0 = mBase & 511;
        const uint4* src = (const uint4*)&T[row][part * 64];
        uint4* dst = (uint4*)(d_vh + ((size_t)hh * NN + (size_t)s * CH + c) * I_ + j0 + part * 64);
#pragma unroll
        for (int q = 0; q < 8; q++) dst[q] = src[q];
    } else {
        // g: sigmoid, direct fp32 stores (32B segments, fine)
#pragma unroll
        for (int mt = 0; mt < 4; mt++) {
            int R0 = mBase + wr * 64 + mt * 16 + g;
            int R1 = R0 + 8;
#pragma unroll
            for (int nt = 0; nt < 4; nt++) {
                int cg = (nBase - 256) + wc * 32 + nt * 8 + 2 * tg;
                float2 o0 = make_float2(1.f / (1.f + __expf(-acc[mt][nt][0])),
                                        1.f / (1.f + __expf(-acc[mt][nt][1])));
                float2 o1 = make_float2(1.f / (1.f + __expf(-acc[mt][nt][2])),
                                        1.f / (1.f + __expf(-acc[mt][nt][3])));
                *(float2*)(d_gbuf + (size_t)R0 * HC + cg) = o0;
                *(float2*)(d_gbuf + (size_t)R1 * HC + cg) = o1;
            }
        }
    }
}

// ---- K3: b = LN(z).W_b^T + INF*(zmask-1).  8 lanes per (i,j) row. ----
__global__ void __launch_bounds__(256) k_b2(const float* __restrict__ z,
                                            const float* __restrict__ zg,
                                            const float* __restrict__ zb,
                                            const float* __restrict__ Wb,
                                            const float* __restrict__ zmask) {
    __shared__ __align__(16) float Wbs[H_ * CZ];
    __shared__ __align__(16) float zgs[CZ], zbs[CZ];
    __shared__ float outs[32][9];
    int t = threadIdx.x;
    for (int idx = t; idx < H_ * CZ; idx += 256) Wbs[idx] = Wb[idx];
    if (t < CZ) { zgs[t] = zg[t]; zbs[t] = zb[t]; }
    __syncthreads();

    int grp = t >> 3, sub = t & 7;
    int w = blockIdx.x * 32 + grp;
    const float* zp = z + (size_t)w * CZ + sub * 16;
    float4 v[4];
#pragma unroll
    for (int q = 0; q < 4; q++) v[q] = *(const float4*)(zp + q * 4);
    float s = 0.f, ss = 0.f;
#pragma unroll
    for (int q = 0; q < 4; q++) {
        s  += v[q].x + v[q].y + v[q].z + v[q].w;
        ss += v[q].x * v[q].x + v[q].y * v[q].y + v[q].z * v[q].z + v[q].w * v[q].w;
    }
#pragma unroll
    for (int o = 4; o; o >>= 1) {
        s  += __shfl_xor_sync(0xffffffffu, s, o);
        ss += __shfl_xor_sync(0xffffffffu, ss, o);
    }
    float mu = s * (1.f / 128.f);
    float var = ss * (1.f / 128.f) - mu * mu;
    float rs = rsqrtf(var + EPS);

    float xn[16];
#pragma unroll
    for (int q = 0; q < 4; q++) {
        float4 g4 = *(const float4*)(zgs + sub * 16 + q * 4);
        float4 b4 = *(const float4*)(zbs + sub * 16 + q * 4);
        xn[q * 4 + 0] = (v[q].x - mu) * rs * g4.x + b4.x;
        xn[q * 4 + 1] = (v[q].y - mu) * rs * g4.y + b4.y;
        xn[q * 4 + 2] = (v[q].z - mu) * rs * g4.z + b4.z;
        xn[q * 4 + 3] = (v[q].w - mu) * rs * g4.w + b4.w;
    }
    float p[8];
#pragma unroll
    for (int h = 0; h < 8; h++) {
        float a = 0.f;
#pragma unroll
        for (int q = 0; q < 4; q++) {
            float4 w4 = *(const float4*)(Wbs + h * CZ + sub * 16 + q * 4);
            a += xn[q * 4 + 0] * w4.x + xn[q * 4 + 1] * w4.y +
                 xn[q * 4 + 2] * w4.z + xn[q * 4 + 3] * w4.w;
        }
        p[h] = a;
    }
    // 3-level payload-halving butterfly over 8 lanes; lane 'sub' ends with head 'sub'
    bool b4_ = sub & 4, b2_ = sub & 2, b1_ = sub & 1;
    float q4[4];
#pragma unroll
    for (int h = 0; h < 4; h++) {
        float send = b4_ ? p[h] : p[h + 4];
        float recv = __shfl_xor_sync(0xffffffffu, send, 4);
        q4[h] = (b4_ ? p[h + 4] : p[h]) + recv;
    }
    float r2[2];
#pragma unroll
    for (int h = 0; h < 2; h++) {
        float send = b2_ ? q4[h] : q4[h + 2];
        float recv = __shfl_xor_sync(0xffffffffu, send, 2);
        r2[h] = (b2_ ? q4[h + 2] : q4[h]) + recv;
    }
    float send = b1_ ? r2[0] : r2[1];
    float recv = __shfl_xor_sync(0xffffffffu, send, 1);
    float val = (b1_ ? r2[1] : r2[0]) + recv;
    outs[grp][sub] = val;
    __syncthreads();

    int w0 = blockIdx.x * 32;
    int i = w0 >> 9, j0 = w0 & 511;
    int hh = t >> 5, jj = t & 31;
    float mval = zmask[w0 + jj];
    d_bw[((size_t)hh * I_ + i) * I_ + j0 + jj] = outs[jj][hh] + 1e8f * (mval - 1.f);
}

// ---------------- K4: softmax over j; output fp16 ----------------
__global__ void k_softmax() {
    int row  = blockIdx.x * 8 + (threadIdx.x >> 5);
    int lane = threadIdx.x & 31;
    const float* p = d_bw + (size_t)row * I_;
    float4 x[4];
#pragma unroll
    for (int q = 0; q < 4; q++) x[q] = *(const float4*)(p + q * 128 + lane * 4);
    float mx = -3.4e38f;
#pragma unroll
    for (int q = 0; q < 4; q++)
        mx = fmaxf(mx, fmaxf(fmaxf(x[q].x, x[q].y), fmaxf(x[q].z, x[q].w)));
    mx = warp_max(mx);
    float sum = 0.f;
#pragma unroll
    for (int q = 0; q < 4; q++) {
        x[q].x = __expf(x[q].x - mx); x[q].y = __expf(x[q].y - mx);
        x[q].z = __expf(x[q].z - mx); x[q].w = __expf(x[q].w - mx);
        sum += x[q].x + x[q].y + x[q].z + x[q].w;
    }
    sum = warp_sum(sum);
    float inv = 1.f / sum;
    __half* wp = d_wh + (size_t)row * I_;
#pragma unroll
    for (int q = 0; q < 4; q++) {
        __half2 h01 = __floats2half2_rn(x[q].x * inv, x[q].y * inv);
        __half2 h23 = __floats2half2_rn(x[q].z * inv, x[q].w * inv);
        *(uint2*)(wp + q * 128 + lane * 4) =
            make_uint2(*(unsigned*)&h01, *(unsigned*)&h23);
    }
}

// ---- K5: einsum via fp16 m16n8k16; output fp16. ----
__global__ void __launch_bounds__(256) k_einsum_h() {
    extern __shared__ __half smh[];
    const int BUF = 15360;
    int t = threadIdx.x, lane = t & 31, wid = t >> 5;
    int g = lane >> 2, tg = lane & 3;
    int wr = wid & 1, wc = wid >> 1;
    int h = blockIdx.z;
    int mBase = blockIdx.y * 128, nBase = blockIdx.x * 256;
    const __half* Ag = d_wh + ((size_t)h * I_ + mBase) * I_;
    const __half* Bg = d_vh + ((size_t)h * NN + nBase) * I_;
    __half*       C  = d_oh + ((size_t)h * I_ + mBase) * NN + nBase;

    int arow = t & 127, ac4 = t >> 7;
    int brow = t;

    {
        const __half* Ap = Ag + (size_t)arow * I_;
        *(uint4*)&smh[arow * 40 + ac4 * 8]       = *(const uint4*)(Ap + ac4 * 8);
        *(uint4*)&smh[arow * 40 + (ac4 + 2) * 8] = *(const uint4*)(Ap + (ac4 + 2) * 8);
        const __half* Bp = Bg + (size_t)brow * I_;
#pragma unroll
        for (int q = 0; q < 4; q++)
            *(uint4*)&smh[5120 + brow * 40 + q * 8] = *(const uint4*)(Bp + q * 8);
    }
    __syncthreads();

    float acc[4][8][4];
#pragma unroll
    for (int a = 0; a < 4; a++)
#pragma unroll
        for (int b = 0; b < 8; b++)
#pragma unroll
            for (int c = 0; c < 4; c++) acc[a][b][c] = 0.f;

    uint4 pa0, pa1, pb[4];
    for (int kc = 0; kc < 16; kc++) {
        int cur = kc & 1;
        if (kc < 15) {
            const __half* Ap = Ag + (size_t)arow * I_ + (kc + 1) * 32;
            pa0 = *(const uint4*)(Ap + ac4 * 8);
            pa1 = *(const uint4*)(Ap + (ac4 + 2) * 8);
            const __half* Bp = Bg + (size_t)brow * I_ + (kc + 1) * 32;
#pragma unroll
            for (int q = 0; q < 4; q++) pb[q] = *(const uint4*)(Bp + q * 8);
        }
        const __half* As = smh + cur * BUF;
        const __half* Bs = smh + cur * BUF + 5120;
#pragma unroll
        for (int ks = 0; ks < 2; ks++) {
            int k0 = ks * 16;
            uint32_t Af[4][4], Bf[8][2];
#pragma unroll
            for (int mt = 0; mt < 4; mt++) {
                int m0 = wr * 64 + mt * 16 + g;
                Af[mt][0] = *(const uint32_t*)&As[(m0)     * 40 + k0 + 2 * tg];
                Af[mt][1] = *(const uint32_t*)&As[(m0 + 8) * 40 + k0 + 2 * tg];
                Af[mt][2] = *(const uint32_t*)&As[(m0)     * 40 + k0 + 2 * tg + 8];
                Af[mt][3] = *(const uint32_t*)&As[(m0 + 8) * 40 + k0 + 2 * tg + 8];
            }
#pragma unroll
            for (int nt = 0; nt < 8; nt++) {
                int n0 = wc * 64 + nt * 8 + g;
                Bf[nt][0] = *(const uint32_t*)&Bs[n0 * 40 + k0 + 2 * tg];
                Bf[nt][1] = *(const uint32_t*)&Bs[n0 * 40 + k0 + 2 * tg + 8];
            }
#pragma unroll
            for (int mt = 0; mt < 4; mt++)
#pragma unroll
                for (int nt = 0; nt < 8; nt++)
                    MMA_F16(acc[mt][nt][0], acc[mt][nt][1], acc[mt][nt][2], acc[mt][nt][3],
                            Af[mt][0], Af[mt][1], Af[mt][2], Af[mt][3],
                            Bf[nt][0], Bf[nt][1]);
        }
        if (kc < 15) {
            __half* Ad = smh + (cur ^ 1) * BUF;
            *(uint4*)&Ad[arow * 40 + ac4 * 8]       = pa0;
            *(uint4*)&Ad[arow * 40 + (ac4 + 2) * 8] = pa1;
            __half* Bd = Ad + 5120;
#pragma unroll
            for (int q = 0; q < 4; q++) *(uint4*)&Bd[brow * 40 + q * 8] = pb[q];
            __syncthreads();
        }
    }

#pragma unroll
    for (int mt = 0; mt < 4; mt++) {
        int r = wr * 64 + mt * 16 + g;
#pragma unroll
        for (int nt = 0; nt < 8; nt++) {
            int col = wc * 64 + nt * 8 + 2 * tg;
            __half2 h0 = __floats2half2_rn(acc[mt][nt][0], acc[mt][nt][1]);
            __half2 h1 = __floats2half2_rn(acc[mt][nt][2], acc[mt][nt][3]);
            *(__half2*)(C + (size_t)r * NN + col)       = h0;
            *(__half2*)(C + (size_t)(r + 8) * NN + col) = h1;
        }
    }
}

// ---- K6: out = (g * gather(o)) @ W_o^T ----
__global__ void __launch_bounds__(256) k_out(const float* __restrict__ Wo,
                                             float* __restrict__ out) {
    extern __shared__ float sm[];
    float* WoT = sm;              // [256][68]
    float* aT  = sm + 256 * 68;   // [256][68]
    int t = threadIdx.x;
#pragma unroll 4
    for (int q = 0; q < 64; q++) {
        int idx = q * 256 + t;
        int cm = idx >> 8, k = idx & 255;
        WoT[k * 68 + cm] = Wo[idx];
    }
    int rowBase = blockIdx.x * 64;
#pragma unroll 4
    for (int q = 0; q < 64; q++) {
        int idx = q * 256 + t;
        int r = idx >> 8, kk = idx & 255;
        int gr = rowBase + r;
        int s = gr >> 9, i = gr & 511;
        int h = kk >> 5, c = kk & 31;
        float gv = d_gbuf[(size_t)gr * HC + kk];
        float ov = __half2float(d_oh[((size_t)h * I_ + i) * NN + s * CH + c]);
        aT[kk * 68 + r] = gv * ov;
    }
    __syncthreads();
    int tx = t & 15, ty = t >> 4;
    float acc[4][4];
#pragma unroll
    for (int r = 0; r < 4; r++)
#pragma unroll
        for (int c = 0; c < 4; c++) acc[r][c] = 0.f;

#pragma unroll 4
    for (int k = 0; k < 256; k++) {
        float4 w4 = *(const float4*)(WoT + k * 68 + tx * 4);
        float4 a4 = *(const float4*)(aT  + k * 68 + ty * 4);
        acc[0][0] += a4.x * w4.x; acc[0][1] += a4.x * w4.y;
        acc[0][2] += a4.x * w4.z; acc[0][3] += a4.x * w4.w;
        acc[1][0] += a4.y * w4.x; acc[1][1] += a4.y * w4.y;
        acc[1][2] += a4.y * w4.z; acc[1][3] += a4.y * w4.w;
        acc[2][0] += a4.z * w4.x; acc[2][1] += a4.z * w4.y;
        acc[2][2] += a4.z * w4.z; acc[2][3] += a4.z * w4.w;
        acc[3][0] += a4.w * w4.x; acc[3][1] += a4.w * w4.y;
        acc[3][2] += a4.w * w4.z; acc[3][3] += a4.w * w4.w;
    }
#pragma unroll
    for (int r = 0; r < 4; r++) {
        *(float4*)(out + (size_t)(rowBase + ty * 4 + r) * CM + tx * 4) =
            make_float4(acc[r][0], acc[r][1], acc[r][2], acc[r][3]);
    }
}

extern "C" void kernel_launch(void* const* d_in, const int* in_sizes, int n_in,
                              void* d_out, int out_size) {
    const float* m        = (const float*)d_in[0];
    const float* z        = (const float*)d_in[1];
    const float* msa_mask = (const float*)d_in[2];
    const float* z_mask   = (const float*)d_in[3];
    const float* ln_m_g   = (const float*)d_in[4];
    const float* ln_m_b   = (const float*)d_in[5];
    const float* W_v      = (const float*)d_in[6];
    const float* W_g      = (const float*)d_in[7];
    const float* ln_z_g   = (const float*)d_in[8];
    const float* ln_z_b   = (const float*)d_in[9];
    const float* W_b      = (const float*)d_in[10];
    const float* W_o      = (const float*)d_in[11];
    float* out = (float*)d_out;

    const int SMEM_VG  = (128 * 68 + 64 * 132) * 4;   // 68608
    const int SMEM_OUT = (256 * 68 * 2) * 4;          // 139264
    const int SMEM_EIN = 2 * 15360 * 2;               // 61440
    cudaFuncSetAttribute(k_vg_tc,   cudaFuncAttributeMaxDynamicSharedMemorySize, SMEM_VG);
    cudaFuncSetAttribute(k_out,     cudaFuncAttributeMaxDynamicSharedMemorySize, SMEM_OUT);
    cudaFuncSetAttribute(k_einsum_h,cudaFuncAttributeMaxDynamicSharedMemorySize, SMEM_EIN);

    k_ln_m<<<S_ * I_ / 8, 256>>>(m, ln_m_g, ln_m_b);
    k_vg_tc<<<dim3(4, 1024), 256, SMEM_VG>>>(W_v, W_g, msa_mask);
    k_b2<<<I_ * I_ / 32, 256>>>(z, ln_z_g, ln_z_b, W_b, z_mask);
    k_softmax<<<H_ * I_ / 8, 256>>>();
    k_einsum_h<<<dim3(NN / 256, I_ / 128, H_), 256, SMEM_EIN>>>();
    k_out<<<S_ * I_ / 64, 256, SMEM_OUT>>>(W_o, out);
}